// round 14
// baseline (speedup 1.0000x reference)
#include <cuda_runtime.h>
#include <stdint.h>
#include <stdlib.h>
#include <math.h>

// ---------------- problem constants ----------------
#define HW 256
#define NPIXC (HW*HW)          // 65536
#define S2 2048
#define NPIX (S2*S2)           // 4194304
#define CAP (1<<17)            // candidate capacity (131072 = 128 chunks of 1024)
#define THRESH 0.005f

// ---------------- device scratch: ONE 64 MiB pool, phase-disjoint overlays --------
#define POOL_BYTES (64u*1024u*1024u)
__device__ __align__(1024) unsigned char g_pool[POOL_BYTES];
__device__ float g_scores[NPIX];              // 16 MiB
__device__ int g_count;

#define OFF_T0    (0u)
#define OFF_T1    (16u<<20)
#define OFF_MASK  (48u<<20)
#define OFF_MSUP  (52u<<20)
#define OFF_MTMP  (56u<<20)
#define OFF_KEYSA (60u<<20)
#define OFF_KEYSB (61u<<20)

namespace {
struct SetEagerLoading {
    SetEagerLoading() { setenv("CUDA_MODULE_LOADING", "EAGER", 1); }
};
SetEagerLoading _set_eager_loading;
}

__device__ __forceinline__ unsigned int smem_u32(const void* p) {
    return (unsigned int)__cvta_generic_to_shared(p);
}

// conv1 dynamic smem layout (floats):
//   [0 .. 9248)                 : input tile buffer 0 (8*34*34 = 9248)
//   [9248 .. 18496)             : input tile buffer 1
//   [18496 .. 18496 + 9216)     : all weights, 16 chunks x 72 x 8
#define TILE_F   (8*34*34)                 // 9248 floats
#define CONV1_DYN_FLOATS (2*TILE_F + 16*72*8)
#define CONV1_DYN_BYTES  (CONV1_DYN_FLOATS * 4)   // 110848 B

// ---------------- conv1: 3x3, 128->256, ReLU ----------------
// block (16,16), thread = 2x2 px, 8 oc/block, grid (8,8,32).
// Math: per-ic 9-tap fp32 partial v_ (ky-major, kx inner — identical chain to
// the passing kernels) folded DIRECTLY into double accumulators. This removes
// the 384 FADD/thread/chunk of b_/Kahan bookkeeping from the binding FMA pipe
// (DADD/F2F ride the separate FP64 pipe) and cuts live registers ~180 -> ~140.
// Accuracy: exact double sum of the 128 per-ic partials (better than Kahan);
// score perturbation ~1 ulp of mid, far inside the passing 1.9e-7 band.
// Data movement unchanged from R13: all weights preloaded, cp.async
// double-buffered input tiles (zero-fill halo).
__global__ __launch_bounds__(256, 1) void k_conv1(const float* __restrict__ in,
                                                  const float* __restrict__ wA,
                                                  const float* __restrict__ bA,
                                                  float* __restrict__ mid) {
    extern __shared__ __align__(16) float dyn[];
    float* sIn0  = dyn;                    // tile buf 0
    float* sIn1  = dyn + TILE_F;           // tile buf 1
    float* sWall = dyn + 2*TILE_F;         // [chunk][ick][oc] = chunk*576 + ick*8 + oc

    const int tx = threadIdx.x, ty = threadIdx.y;
    const int tid = ty * 16 + tx;
    const int x0 = blockIdx.x * 32, y0 = blockIdx.y * 32;
    const int ocb = blockIdx.z * 8;

    // preload ALL weights for this oc-block: 16 chunks x 8 ic x 9 taps x 8 oc
    for (int l = tid; l < 16 * 576; l += 256) {
        int chunk = l / 576; int r = l % 576;
        int oc = r & 7; int ick = r >> 3;          // ick in [0,72)
        int ic = ick / 9, k = ick % 9;
        sWall[chunk * 576 + ick * 8 + oc] =
            wA[(ocb + oc) * 1152 + (chunk * 8 + ic) * 9 + k];
    }

    // async tile loader: chunk ch -> buffer buf (zero-fill outside image)
    auto issue_tile = [&](int ch, float* buf) {
        for (int l = tid; l < TILE_F; l += 256) {
            int ic = l / 1156; int r = l % 1156; int yy = r / 34; int xx = r % 34;
            int gy = y0 + yy - 1, gx = x0 + xx - 1;
            bool inb = ((unsigned)gy < 256u) && ((unsigned)gx < 256u);
            const float* src = inb ? (in + (ch * 8 + ic) * NPIXC + gy * 256 + gx) : in;
            int sz = inb ? 4 : 0;
            unsigned int dst = smem_u32(buf + l);
            asm volatile("cp.async.ca.shared.global [%0], [%1], 4, %2;"
                         :: "r"(dst), "l"(src), "r"(sz));
        }
        asm volatile("cp.async.commit_group;");
    };
    issue_tile(0, sIn0);

    double acc_d[8][4];
#pragma unroll
    for (int o = 0; o < 8; o++)
#pragma unroll
        for (int p = 0; p < 4; p++) acc_d[o][p] = 0.0;

    for (int c = 0; c < 16; c++) {
        if (c + 1 < 16) {
            issue_tile(c + 1, ((c + 1) & 1) ? sIn1 : sIn0);
            asm volatile("cp.async.wait_group 1;");
        } else {
            asm volatile("cp.async.wait_group 0;");
        }
        __syncthreads();   // tile c visible; also covers weight preload at c=0

        const float* S = (c & 1) ? sIn1 : sIn0;

        for (int ic = 0; ic < 8; ic++) {
            // hoist 4x4 input patch to registers (8B-aligned LDS.64 pairs)
            float ir[4][4];
#pragma unroll
            for (int r = 0; r < 4; r++) {
                const float* rowp = S + ic * 1156 + (2*ty + r) * 34 + 2*tx;
                float2 a = *(const float2*)rowp;
                float2 b = *(const float2*)(rowp + 2);
                ir[r][0] = a.x; ir[r][1] = a.y; ir[r][2] = b.x; ir[r][3] = b.y;
            }

            float v_[8][4];
#pragma unroll
            for (int o = 0; o < 8; o++)
#pragma unroll
                for (int p = 0; p < 4; p++) v_[o][p] = 0.f;

#pragma unroll
            for (int ky = 0; ky < 3; ky++) {
#pragma unroll
                for (int kx = 0; kx < 3; kx++) {
                    float i00 = ir[ky  ][kx  ];
                    float i01 = ir[ky  ][kx+1];
                    float i10 = ir[ky+1][kx  ];
                    float i11 = ir[ky+1][kx+1];
                    const float4* w4 =
                        (const float4*)(sWall + c * 576 + (ic*9 + ky*3 + kx) * 8);
                    float4 wa = w4[0], wb = w4[1];
                    float wv[8] = {wa.x, wa.y, wa.z, wa.w, wb.x, wb.y, wb.z, wb.w};
#pragma unroll
                    for (int oc = 0; oc < 8; oc++) {
                        float w = wv[oc];
                        v_[oc][0] += i00 * w;
                        v_[oc][1] += i01 * w;
                        v_[oc][2] += i10 * w;
                        v_[oc][3] += i11 * w;
                    }
                }
            }
            // fold per-ic partial into double accumulators (FP64 pipe)
#pragma unroll
            for (int o = 0; o < 8; o++)
#pragma unroll
                for (int p = 0; p < 4; p++) acc_d[o][p] += (double)v_[o][p];
        }
        __syncthreads();   // reads of buffer (c&1) done before iter c+2 rewrites it
    }

    const int gy = y0 + 2*ty, gx = x0 + 2*tx;
#pragma unroll
    for (int oc = 0; oc < 8; oc++) {
        float b = bA[ocb + oc];
        float* mp = &mid[(ocb + oc) * NPIXC];
        mp[gy*256 + gx]       = fmaxf((float)acc_d[oc][0] + b, 0.f);
        mp[gy*256 + gx + 1]   = fmaxf((float)acc_d[oc][1] + b, 0.f);
        mp[(gy+1)*256 + gx]   = fmaxf((float)acc_d[oc][2] + b, 0.f);
        mp[(gy+1)*256 + gx+1] = fmaxf((float)acc_d[oc][3] + b, 0.f);
    }
}

// ---------------- conv2 (1x1, 256->65) + double softmax + depth-to-space ---------
__global__ __launch_bounds__(256) void k_conv2(const float* __restrict__ mid,
                                               const float* __restrict__ wB,
                                               const float* __restrict__ bB) {
    __shared__ float sMid[64][64];
    __shared__ float sW[64][68];
    __shared__ float sB[68];

    const int tid = threadIdx.x;
    const int t = tid & 3;
    const int pi = tid >> 2;
    const int pix0 = blockIdx.x * 64;
    const int pix = pix0 + pi;

    if (tid < 68) sB[tid] = (tid < 65) ? bB[tid] : 0.f;
    for (int l = tid; l < 64 * 3; l += 256) {
        int c = l / 3, pc = l % 3;
        sW[c][65 + pc] = 0.f;
    }

    double dacc[17];
#pragma unroll
    for (int j = 0; j < 17; j++) dacc[j] = 0.0;

    for (int c0 = 0; c0 < 256; c0 += 64) {
        __syncthreads();
        for (int l = tid; l < 64 * 65; l += 256) {
            int c = l / 65, oc = l % 65;
            sW[c][oc] = wB[oc * 256 + c0 + c];
        }
        for (int l = tid; l < 64 * 64; l += 256) {
            int c = l >> 6, p = l & 63;
            sMid[c][p] = mid[(c0 + c) * NPIXC + pix0 + p];
        }
        __syncthreads();
        float p_[17];
#pragma unroll
        for (int j = 0; j < 17; j++) p_[j] = 0.f;
        for (int c = 0; c < 64; c++) {
            float m = sMid[c][pi];
#pragma unroll
            for (int j = 0; j < 17; j++)
                p_[j] += m * sW[c][4 * j + t];
        }
#pragma unroll
        for (int j = 0; j < 17; j++) dacc[j] += (double)p_[j];
    }
#pragma unroll
    for (int j = 0; j < 17; j++) dacc[j] += (double)sB[4 * j + t];

    double mx = -1e300;
#pragma unroll
    for (int j = 0; j < 17; j++) if (4 * j + t < 65) mx = fmax(mx, dacc[j]);
    mx = fmax(mx, __shfl_xor_sync(0xFFFFFFFFu, mx, 1));
    mx = fmax(mx, __shfl_xor_sync(0xFFFFFFFFu, mx, 2));
    double sum = 0.0;
#pragma unroll
    for (int j = 0; j < 17; j++) {
        if (4 * j + t < 65) { dacc[j] = exp(dacc[j] - mx); sum += dacc[j]; }
    }
    sum += __shfl_xor_sync(0xFFFFFFFFu, sum, 1);
    sum += __shfl_xor_sync(0xFFFFFFFFu, sum, 2);
    double inv = 1.0 / sum;

    const int h = pix >> 8, w = pix & 255;
#pragma unroll
    for (int j = 0; j < 17; j++) {
        int oc = 4 * j + t;
        if (oc < 64) {
            int r = oc >> 3, c = oc & 7;
            g_scores[(h * 8 + r) * S2 + (w * 8 + c)] = (float)(dacc[j] * inv);
        }
    }
}

// ---------------- NMS: vectorized separable 9-max / dilation ----------------
#define NEG_INF (-1e30f)
__global__ void k_rowmax4(const float* __restrict__ in, float* __restrict__ out) {
    int t4 = blockIdx.x * 256 + threadIdx.x;
    int y = t4 >> 9, x0 = (t4 & 511) << 2;
    const float* row = in + (y << 11);
    float4 m4 = *(const float4*)(row + x0);
    float4 a4 = (x0 >= 4)    ? *(const float4*)(row + x0 - 4)
                             : make_float4(NEG_INF, NEG_INF, NEG_INF, NEG_INF);
    float4 c4 = (x0 <= 2040) ? *(const float4*)(row + x0 + 4)
                             : make_float4(NEG_INF, NEG_INF, NEG_INF, NEG_INF);
    float C = fmaxf(fmaxf(fmaxf(a4.w, m4.x), fmaxf(m4.y, m4.z)), fmaxf(m4.w, c4.x));
    float4 o;
    o.x = fmaxf(C, fmaxf(a4.x, fmaxf(a4.y, a4.z)));
    o.y = fmaxf(C, fmaxf(a4.y, fmaxf(a4.z, c4.y)));
    o.z = fmaxf(C, fmaxf(a4.z, fmaxf(c4.y, c4.z)));
    o.w = fmaxf(C, fmaxf(c4.y, fmaxf(c4.z, c4.w)));
    *(float4*)(out + (y << 11) + x0) = o;
}
__global__ void k_colmax_eq4(const float* __restrict__ t1,
                             unsigned char* __restrict__ mask) {
    int t4 = blockIdx.x * 256 + threadIdx.x;
    int y = t4 >> 9, x0 = (t4 & 511) << 2;
    int ya = max(y - 4, 0), yb = min(y + 4, 2047);
    float4 m = make_float4(NEG_INF, NEG_INF, NEG_INF, NEG_INF);
    for (int yy = ya; yy <= yb; yy++) {
        float4 v = *(const float4*)(t1 + (yy << 11) + x0);
        m.x = fmaxf(m.x, v.x); m.y = fmaxf(m.y, v.y);
        m.z = fmaxf(m.z, v.z); m.w = fmaxf(m.w, v.w);
    }
    float4 s = *(const float4*)(g_scores + (y << 11) + x0);
    uchar4 o;
    o.x = (s.x == m.x); o.y = (s.y == m.y); o.z = (s.z == m.z); o.w = (s.w == m.w);
    *(uchar4*)(mask + (y << 11) + x0) = o;
}
__global__ void k_rowor4(const unsigned char* __restrict__ in,
                         unsigned char* __restrict__ out) {
    int t4 = blockIdx.x * 256 + threadIdx.x;
    int y = t4 >> 9, x0 = (t4 & 511) << 2;
    const unsigned char* row = in + (y << 11);
    unsigned int b = *(const unsigned int*)(row + x0);
    unsigned int a = (x0 >= 4)    ? *(const unsigned int*)(row + x0 - 4) : 0u;
    unsigned int c = (x0 <= 2040) ? *(const unsigned int*)(row + x0 + 4) : 0u;
    unsigned long long lo = (unsigned long long)a | ((unsigned long long)b << 32);
    unsigned long long hi = (unsigned long long)b | ((unsigned long long)c << 32);
    unsigned int o = 0;
#pragma unroll
    for (int k = 0; k < 5; k++) {
        o |= (unsigned int)(lo >> (8 * k));
        o |= (unsigned int)(hi >> (8 * k));
    }
    *(unsigned int*)(out + (y << 11) + x0) = o;
}
__global__ void k_color_supp4(const unsigned char* __restrict__ mtmp,
                              unsigned char* __restrict__ msup,
                              float* __restrict__ t0) {
    int t4 = blockIdx.x * 256 + threadIdx.x;
    int y = t4 >> 9, x0 = (t4 & 511) << 2;
    int ya = max(y - 4, 0), yb = min(y + 4, 2047);
    unsigned int sup = 0;
    for (int yy = ya; yy <= yb; yy++)
        sup |= *(const unsigned int*)(mtmp + (yy << 11) + x0);
    *(unsigned int*)(msup + (y << 11) + x0) = sup;
    float4 s = *(const float4*)(g_scores + (y << 11) + x0);
    float4 o;
    o.x = (sup & 0x000000FFu) ? 0.f : s.x;
    o.y = (sup & 0x0000FF00u) ? 0.f : s.y;
    o.z = (sup & 0x00FF0000u) ? 0.f : s.z;
    o.w = (sup & 0xFF000000u) ? 0.f : s.w;
    *(float4*)(t0 + (y << 11) + x0) = o;
}
__global__ void k_colmax_upd4(const float* __restrict__ t1,
                              const unsigned char* __restrict__ msup,
                              unsigned char* __restrict__ mask) {
    int t4 = blockIdx.x * 256 + threadIdx.x;
    int y = t4 >> 9, x0 = (t4 & 511) << 2;
    int ya = max(y - 4, 0), yb = min(y + 4, 2047);
    float4 m = make_float4(NEG_INF, NEG_INF, NEG_INF, NEG_INF);
    for (int yy = ya; yy <= yb; yy++) {
        float4 v = *(const float4*)(t1 + (yy << 11) + x0);
        m.x = fmaxf(m.x, v.x); m.y = fmaxf(m.y, v.y);
        m.z = fmaxf(m.z, v.z); m.w = fmaxf(m.w, v.w);
    }
    float4 s = *(const float4*)(g_scores + (y << 11) + x0);
    uchar4 sp = *(const uchar4*)(msup + (y << 11) + x0);
    uchar4 mk = *(uchar4*)(mask + (y << 11) + x0);
    if (!sp.x && s.x == m.x) mk.x = 1;
    if (!sp.y && s.y == m.y) mk.y = 1;
    if (!sp.z && s.z == m.z) mk.z = 1;
    if (!sp.w && s.w == m.w) mk.w = 1;
    *(uchar4*)(mask + (y << 11) + x0) = mk;
}

// ---------------- candidate extraction ----------------
__global__ void k_reset() { g_count = 0; }

__global__ void k_compact(const unsigned char* __restrict__ mask,
                          unsigned long long* __restrict__ keys) {
    int idx = blockIdx.x * 256 + threadIdx.x;
    if (!mask[idx]) return;
    float v = g_scores[idx];
    int y = idx >> 11, x = idx & 2047;
    // reference upper-border check is vacuous (H8*8-4 = 16380 > 2047)
    if (v > THRESH && y >= 4 && x >= 4) {
        int p = atomicAdd(&g_count, 1);
        if (p < CAP)
            keys[p] = ((unsigned long long)__float_as_uint(v) << 32) |
                      (unsigned int)(~(unsigned int)idx);
    }
}

// ---------------- per-chunk bitonic sort (descending) ----------------
__global__ __launch_bounds__(1024) void k_presort(unsigned long long* __restrict__ keys) {
    __shared__ unsigned long long sk[1024];
    const int i = threadIdx.x;
    const int gi = blockIdx.x * 1024 + i;
    int count = min(g_count, CAP);
    sk[i] = (gi < count) ? keys[gi] : 0ULL;
    __syncthreads();
    for (int k = 2; k <= 1024; k <<= 1) {
        for (int j = k >> 1; j > 0; j >>= 1) {
            int ixj = i ^ j;
            if (ixj > i) {
                bool desc = ((i & k) == 0);
                unsigned long long a = sk[i], b = sk[ixj];
                if (desc ? (a < b) : (a > b)) { sk[i] = b; sk[ixj] = a; }
            }
            __syncthreads();
        }
    }
    keys[gi] = sk[i];
}

// ---------------- tournament pair-merge: top-1024 of two sorted 1024 lists -------
__global__ __launch_bounds__(1024) void k_merge_pair(const unsigned long long* __restrict__ src,
                                                     unsigned long long* __restrict__ dst) {
    __shared__ unsigned long long C[1024];
    const int i = threadIdx.x;
    const int b = blockIdx.x;
    unsigned long long a = src[(2*b) * 1024 + i];
    unsigned long long q = src[(2*b + 1) * 1024 + (1023 - i)];
    C[i] = (a > q) ? a : q;        // bitonic; contains top-1024 of the union
    __syncthreads();
    for (int j = 512; j > 0; j >>= 1) {
        int ixj = i ^ j;
        if (ixj > i) {
            unsigned long long u = C[i], v = C[ixj];
            if (u < v) { C[i] = v; C[ixj] = u; }
        }
        __syncthreads();
    }
    dst[b * 1024 + i] = C[i];
}

// ---------------- final output ----------------
__global__ __launch_bounds__(1024) void k_out(const unsigned long long* __restrict__ top,
                                              float* __restrict__ out) {
    const int i = threadIdx.x;
    int count = min(g_count, CAP);
    int nval = min(count, 1024);
    float kx, ky, sc;
    if (i < nval) {
        unsigned long long key = top[i];
        sc = __uint_as_float((unsigned int)(key >> 32));
        unsigned int idx = ~(unsigned int)key;
        kx = (float)(idx & 2047u);
        ky = (float)(idx >> 11);
    } else {
        int j = i - nval;        // top_k padding: -1 score, smallest invalid indices
        sc = -1.0f;
        kx = (float)j;
        ky = 0.0f;
    }
    out[2*i]      = kx;
    out[2*i + 1]  = ky;
    out[2048 + i] = sc;
}

// ---------------- launch ----------------
extern "C" void kernel_launch(void* const* d_in, const int* in_sizes, int n_in,
                              void* d_out, int out_size) {
    const float* enc = (const float*)d_in[0];
    const float* wA  = (const float*)d_in[1];
    const float* bA  = (const float*)d_in[2];
    const float* wB  = (const float*)d_in[3];
    const float* bB  = (const float*)d_in[4];
    float* out = (float*)d_out;

    static unsigned char* P = nullptr;
    static float* scores = nullptr;
    if (P == nullptr) {
        void* pv = nullptr;
        cudaGetSymbolAddress(&pv, g_pool);
        P = (unsigned char*)pv;
        void* sv = nullptr;
        cudaGetSymbolAddress(&sv, g_scores);
        scores = (float*)sv;
        // one-time, uncaptured: allow conv1's 108 KB dynamic smem
        cudaFuncSetAttribute(k_conv1,
                             cudaFuncAttributeMaxDynamicSharedMemorySize,
                             CONV1_DYN_BYTES);
    }
    float* mid = (float*)P;
    float* t0  = (float*)(P + OFF_T0);
    float* t1  = (float*)(P + OFF_T1);
    unsigned char* mask = P + OFF_MASK;
    unsigned char* msup = P + OFF_MSUP;
    unsigned char* mtmp = P + OFF_MTMP;
    unsigned long long* keysA = (unsigned long long*)(P + OFF_KEYSA);
    unsigned long long* keysB = (unsigned long long*)(P + OFF_KEYSB);

    const int V4 = NPIX / 4 / 256;   // 4096 blocks for 4-px/thread kernels
    const int EB = NPIX / 256;       // 16384 blocks per-pixel

    k_reset<<<1, 1>>>();
    k_conv1<<<dim3(8,8,32), dim3(16,16), CONV1_DYN_BYTES>>>(enc, wA, bA, mid);
    k_conv2<<<1024, 256>>>(mid, wB, bB);

    // initial max mask
    k_rowmax4<<<V4, 256>>>(scores, t1);
    k_colmax_eq4<<<V4, 256>>>(t1, mask);

    for (int it = 0; it < 2; it++) {
        k_rowor4<<<V4, 256>>>(mask, mtmp);
        k_color_supp4<<<V4, 256>>>(mtmp, msup, t0);
        k_rowmax4<<<V4, 256>>>(t0, t1);
        k_colmax_upd4<<<V4, 256>>>(t1, msup, mask);
    }

    k_compact<<<EB, 256>>>(mask, keysA);
    k_presort<<<CAP/1024, 1024>>>(keysA);

    // tournament: 128 chunks -> 1 (ping-pong keysA/keysB)
    k_merge_pair<<<64, 1024>>>(keysA, keysB);
    k_merge_pair<<<32, 1024>>>(keysB, keysA);
    k_merge_pair<<<16, 1024>>>(keysA, keysB);
    k_merge_pair<<<8,  1024>>>(keysB, keysA);
    k_merge_pair<<<4,  1024>>>(keysA, keysB);
    k_merge_pair<<<2,  1024>>>(keysB, keysA);
    k_merge_pair<<<1,  1024>>>(keysA, keysB);

    k_out<<<1, 1024>>>(keysB, out);
}

// round 15
// speedup vs baseline: 1.2322x; 1.2322x over previous
#include <cuda_runtime.h>
#include <stdint.h>
#include <stdlib.h>
#include <math.h>

// ---------------- problem constants ----------------
#define HW 256
#define NPIXC (HW*HW)          // 65536
#define S2 2048
#define NPIX (S2*S2)           // 4194304
#define CAP (1<<17)            // candidate capacity (131072 = 128 chunks of 1024)
#define THRESH 0.005f

// ---------------- device scratch: ONE 64 MiB pool, phase-disjoint overlays --------
#define POOL_BYTES (64u*1024u*1024u)
__device__ __align__(1024) unsigned char g_pool[POOL_BYTES];
__device__ float g_scores[NPIX];              // 16 MiB
__device__ int g_count;

#define OFF_T0    (0u)
#define OFF_T1    (16u<<20)
#define OFF_MASK  (48u<<20)
#define OFF_MSUP  (52u<<20)
#define OFF_MTMP  (56u<<20)
#define OFF_KEYSA (60u<<20)
#define OFF_KEYSB (61u<<20)

namespace {
struct SetEagerLoading {
    SetEagerLoading() { setenv("CUDA_MODULE_LOADING", "EAGER", 1); }
};
SetEagerLoading _set_eager_loading;
}

__device__ __forceinline__ unsigned int smem_u32(const void* p) {
    return (unsigned int)__cvta_generic_to_shared(p);
}

// conv1 dynamic smem layout (floats):
//   [0 .. 18496)            : input tile buffer 0 (16 ic * 34 * 34)
//   [18496 .. 36992)        : input tile buffer 1
//   [36992 .. 36992+9216)   : all weights, 8 chunks x 144 x 8
#define TILE_F   (16*34*34)                // 18496 floats (73.98 KB)
#define CONV1_DYN_FLOATS (2*TILE_F + 8*144*8)
#define CONV1_DYN_BYTES  (CONV1_DYN_FLOATS * 4)   // 184832 B

// ---------------- conv1: 3x3, 128->256, ReLU ----------------
// block (16,16), thread = 2x2 px, 8 oc/block, grid (8,8,32).
// Math (error-equivalent to the passing R13 kernel): per-ic 9-tap fp32 partial
// v_ (ky-major, kx inner) -> per-16-ic chunk partial b_ -> scalar Kahan fold
// into acc. 8 chunks x 16 ic (was 16 x 8): halves Kahan folds (1024 fewer
// FMA-pipe instrs/thread) and halves barriers/cp.async waits; error algebra
// identical (sqrt(8)*16*eps == sqrt(16)*8*eps on the b_ chains; Kahan exact).
// Data movement: all weights preloaded once; cp.async double-buffered tiles.
__global__ __launch_bounds__(256, 1) void k_conv1(const float* __restrict__ in,
                                                  const float* __restrict__ wA,
                                                  const float* __restrict__ bA,
                                                  float* __restrict__ mid) {
    extern __shared__ __align__(16) float dyn[];
    float* sIn0  = dyn;                    // tile buf 0
    float* sIn1  = dyn + TILE_F;           // tile buf 1
    float* sWall = dyn + 2*TILE_F;         // [chunk][ick][oc] = chunk*1152 + ick*8 + oc

    const int tx = threadIdx.x, ty = threadIdx.y;
    const int tid = ty * 16 + tx;
    const int x0 = blockIdx.x * 32, y0 = blockIdx.y * 32;
    const int ocb = blockIdx.z * 8;

    // preload ALL weights for this oc-block: 8 chunks x 16 ic x 9 taps x 8 oc
    for (int l = tid; l < 8 * 1152; l += 256) {
        int chunk = l / 1152; int r = l % 1152;
        int oc = r & 7; int ick = r >> 3;          // ick in [0,144)
        int ic = ick / 9, k = ick % 9;
        sWall[chunk * 1152 + ick * 8 + oc] =
            wA[(ocb + oc) * 1152 + (chunk * 16 + ic) * 9 + k];
    }

    // async tile loader: chunk ch (16 ic) -> buffer buf (zero-fill outside image)
    auto issue_tile = [&](int ch, float* buf) {
        for (int l = tid; l < TILE_F; l += 256) {
            int ic = l / 1156; int r = l % 1156; int yy = r / 34; int xx = r % 34;
            int gy = y0 + yy - 1, gx = x0 + xx - 1;
            bool inb = ((unsigned)gy < 256u) && ((unsigned)gx < 256u);
            const float* src = inb ? (in + (ch * 16 + ic) * NPIXC + gy * 256 + gx) : in;
            int sz = inb ? 4 : 0;
            unsigned int dst = smem_u32(buf + l);
            asm volatile("cp.async.ca.shared.global [%0], [%1], 4, %2;"
                         :: "r"(dst), "l"(src), "r"(sz));
        }
        asm volatile("cp.async.commit_group;");
    };
    issue_tile(0, sIn0);

    float acc[8][4], cmp[8][4];
#pragma unroll
    for (int o = 0; o < 8; o++)
#pragma unroll
        for (int p = 0; p < 4; p++) { acc[o][p] = 0.f; cmp[o][p] = 0.f; }

    for (int c = 0; c < 8; c++) {
        if (c + 1 < 8) {
            issue_tile(c + 1, ((c + 1) & 1) ? sIn1 : sIn0);
            asm volatile("cp.async.wait_group 1;");
        } else {
            asm volatile("cp.async.wait_group 0;");
        }
        __syncthreads();   // tile c visible; also covers weight preload at c=0

        const float* S = (c & 1) ? sIn1 : sIn0;

        float b_[8][4];
#pragma unroll
        for (int o = 0; o < 8; o++)
#pragma unroll
            for (int p = 0; p < 4; p++) b_[o][p] = 0.f;

        for (int ic = 0; ic < 16; ic++) {
            // hoist 4x4 input patch to registers (8B-aligned LDS.64 pairs)
            float ir[4][4];
#pragma unroll
            for (int r = 0; r < 4; r++) {
                const float* rowp = S + ic * 1156 + (2*ty + r) * 34 + 2*tx;
                float2 a = *(const float2*)rowp;
                float2 b = *(const float2*)(rowp + 2);
                ir[r][0] = a.x; ir[r][1] = a.y; ir[r][2] = b.x; ir[r][3] = b.y;
            }

            float v_[8][4];
#pragma unroll
            for (int o = 0; o < 8; o++)
#pragma unroll
                for (int p = 0; p < 4; p++) v_[o][p] = 0.f;

#pragma unroll
            for (int ky = 0; ky < 3; ky++) {
#pragma unroll
                for (int kx = 0; kx < 3; kx++) {
                    float i00 = ir[ky  ][kx  ];
                    float i01 = ir[ky  ][kx+1];
                    float i10 = ir[ky+1][kx  ];
                    float i11 = ir[ky+1][kx+1];
                    const float4* w4 =
                        (const float4*)(sWall + c * 1152 + (ic*9 + ky*3 + kx) * 8);
                    float4 wa = w4[0], wb = w4[1];
                    float wv[8] = {wa.x, wa.y, wa.z, wa.w, wb.x, wb.y, wb.z, wb.w};
#pragma unroll
                    for (int oc = 0; oc < 8; oc++) {
                        float w = wv[oc];
                        v_[oc][0] += i00 * w;
                        v_[oc][1] += i01 * w;
                        v_[oc][2] += i10 * w;
                        v_[oc][3] += i11 * w;
                    }
                }
            }
#pragma unroll
            for (int o = 0; o < 8; o++)
#pragma unroll
                for (int p = 0; p < 4; p++) b_[o][p] += v_[o][p];
        }
        // scalar Kahan fold of chunk partial into acc
#pragma unroll
        for (int o = 0; o < 8; o++)
#pragma unroll
            for (int p = 0; p < 4; p++) {
                float y = b_[o][p] - cmp[o][p];
                float t = acc[o][p] + y;
                cmp[o][p] = (t - acc[o][p]) - y;
                acc[o][p] = t;
            }
        __syncthreads();   // reads of buffer (c&1) done before iter c+2 rewrites it
    }

    const int gy = y0 + 2*ty, gx = x0 + 2*tx;
#pragma unroll
    for (int oc = 0; oc < 8; oc++) {
        float b = bA[ocb + oc];
        float* mp = &mid[(ocb + oc) * NPIXC];
        mp[gy*256 + gx]       = fmaxf(acc[oc][0] + b, 0.f);
        mp[gy*256 + gx + 1]   = fmaxf(acc[oc][1] + b, 0.f);
        mp[(gy+1)*256 + gx]   = fmaxf(acc[oc][2] + b, 0.f);
        mp[(gy+1)*256 + gx+1] = fmaxf(acc[oc][3] + b, 0.f);
    }
}

// ---------------- conv2 (1x1, 256->65) + double softmax + depth-to-space ---------
__global__ __launch_bounds__(256) void k_conv2(const float* __restrict__ mid,
                                               const float* __restrict__ wB,
                                               const float* __restrict__ bB) {
    __shared__ float sMid[64][64];
    __shared__ float sW[64][68];
    __shared__ float sB[68];

    const int tid = threadIdx.x;
    const int t = tid & 3;
    const int pi = tid >> 2;
    const int pix0 = blockIdx.x * 64;
    const int pix = pix0 + pi;

    if (tid < 68) sB[tid] = (tid < 65) ? bB[tid] : 0.f;
    for (int l = tid; l < 64 * 3; l += 256) {
        int c = l / 3, pc = l % 3;
        sW[c][65 + pc] = 0.f;
    }

    double dacc[17];
#pragma unroll
    for (int j = 0; j < 17; j++) dacc[j] = 0.0;

    for (int c0 = 0; c0 < 256; c0 += 64) {
        __syncthreads();
        for (int l = tid; l < 64 * 65; l += 256) {
            int c = l / 65, oc = l % 65;
            sW[c][oc] = wB[oc * 256 + c0 + c];
        }
        for (int l = tid; l < 64 * 64; l += 256) {
            int c = l >> 6, p = l & 63;
            sMid[c][p] = mid[(c0 + c) * NPIXC + pix0 + p];
        }
        __syncthreads();
        float p_[17];
#pragma unroll
        for (int j = 0; j < 17; j++) p_[j] = 0.f;
        for (int c = 0; c < 64; c++) {
            float m = sMid[c][pi];
#pragma unroll
            for (int j = 0; j < 17; j++)
                p_[j] += m * sW[c][4 * j + t];
        }
#pragma unroll
        for (int j = 0; j < 17; j++) dacc[j] += (double)p_[j];
    }
#pragma unroll
    for (int j = 0; j < 17; j++) dacc[j] += (double)sB[4 * j + t];

    double mx = -1e300;
#pragma unroll
    for (int j = 0; j < 17; j++) if (4 * j + t < 65) mx = fmax(mx, dacc[j]);
    mx = fmax(mx, __shfl_xor_sync(0xFFFFFFFFu, mx, 1));
    mx = fmax(mx, __shfl_xor_sync(0xFFFFFFFFu, mx, 2));
    double sum = 0.0;
#pragma unroll
    for (int j = 0; j < 17; j++) {
        if (4 * j + t < 65) { dacc[j] = exp(dacc[j] - mx); sum += dacc[j]; }
    }
    sum += __shfl_xor_sync(0xFFFFFFFFu, sum, 1);
    sum += __shfl_xor_sync(0xFFFFFFFFu, sum, 2);
    double inv = 1.0 / sum;

    const int h = pix >> 8, w = pix & 255;
#pragma unroll
    for (int j = 0; j < 17; j++) {
        int oc = 4 * j + t;
        if (oc < 64) {
            int r = oc >> 3, c = oc & 7;
            g_scores[(h * 8 + r) * S2 + (w * 8 + c)] = (float)(dacc[j] * inv);
        }
    }
}

// ---------------- NMS: vectorized separable 9-max / dilation ----------------
#define NEG_INF (-1e30f)
__global__ void k_rowmax4(const float* __restrict__ in, float* __restrict__ out) {
    int t4 = blockIdx.x * 256 + threadIdx.x;
    int y = t4 >> 9, x0 = (t4 & 511) << 2;
    const float* row = in + (y << 11);
    float4 m4 = *(const float4*)(row + x0);
    float4 a4 = (x0 >= 4)    ? *(const float4*)(row + x0 - 4)
                             : make_float4(NEG_INF, NEG_INF, NEG_INF, NEG_INF);
    float4 c4 = (x0 <= 2040) ? *(const float4*)(row + x0 + 4)
                             : make_float4(NEG_INF, NEG_INF, NEG_INF, NEG_INF);
    float C = fmaxf(fmaxf(fmaxf(a4.w, m4.x), fmaxf(m4.y, m4.z)), fmaxf(m4.w, c4.x));
    float4 o;
    o.x = fmaxf(C, fmaxf(a4.x, fmaxf(a4.y, a4.z)));
    o.y = fmaxf(C, fmaxf(a4.y, fmaxf(a4.z, c4.y)));
    o.z = fmaxf(C, fmaxf(a4.z, fmaxf(c4.y, c4.z)));
    o.w = fmaxf(C, fmaxf(c4.y, fmaxf(c4.z, c4.w)));
    *(float4*)(out + (y << 11) + x0) = o;
}
__global__ void k_colmax_eq4(const float* __restrict__ t1,
                             unsigned char* __restrict__ mask) {
    int t4 = blockIdx.x * 256 + threadIdx.x;
    int y = t4 >> 9, x0 = (t4 & 511) << 2;
    int ya = max(y - 4, 0), yb = min(y + 4, 2047);
    float4 m = make_float4(NEG_INF, NEG_INF, NEG_INF, NEG_INF);
    for (int yy = ya; yy <= yb; yy++) {
        float4 v = *(const float4*)(t1 + (yy << 11) + x0);
        m.x = fmaxf(m.x, v.x); m.y = fmaxf(m.y, v.y);
        m.z = fmaxf(m.z, v.z); m.w = fmaxf(m.w, v.w);
    }
    float4 s = *(const float4*)(g_scores + (y << 11) + x0);
    uchar4 o;
    o.x = (s.x == m.x); o.y = (s.y == m.y); o.z = (s.z == m.z); o.w = (s.w == m.w);
    *(uchar4*)(mask + (y << 11) + x0) = o;
}
__global__ void k_rowor4(const unsigned char* __restrict__ in,
                         unsigned char* __restrict__ out) {
    int t4 = blockIdx.x * 256 + threadIdx.x;
    int y = t4 >> 9, x0 = (t4 & 511) << 2;
    const unsigned char* row = in + (y << 11);
    unsigned int b = *(const unsigned int*)(row + x0);
    unsigned int a = (x0 >= 4)    ? *(const unsigned int*)(row + x0 - 4) : 0u;
    unsigned int c = (x0 <= 2040) ? *(const unsigned int*)(row + x0 + 4) : 0u;
    unsigned long long lo = (unsigned long long)a | ((unsigned long long)b << 32);
    unsigned long long hi = (unsigned long long)b | ((unsigned long long)c << 32);
    unsigned int o = 0;
#pragma unroll
    for (int k = 0; k < 5; k++) {
        o |= (unsigned int)(lo >> (8 * k));
        o |= (unsigned int)(hi >> (8 * k));
    }
    *(unsigned int*)(out + (y << 11) + x0) = o;
}
__global__ void k_color_supp4(const unsigned char* __restrict__ mtmp,
                              unsigned char* __restrict__ msup,
                              float* __restrict__ t0) {
    int t4 = blockIdx.x * 256 + threadIdx.x;
    int y = t4 >> 9, x0 = (t4 & 511) << 2;
    int ya = max(y - 4, 0), yb = min(y + 4, 2047);
    unsigned int sup = 0;
    for (int yy = ya; yy <= yb; yy++)
        sup |= *(const unsigned int*)(mtmp + (yy << 11) + x0);
    *(unsigned int*)(msup + (y << 11) + x0) = sup;
    float4 s = *(const float4*)(g_scores + (y << 11) + x0);
    float4 o;
    o.x = (sup & 0x000000FFu) ? 0.f : s.x;
    o.y = (sup & 0x0000FF00u) ? 0.f : s.y;
    o.z = (sup & 0x00FF0000u) ? 0.f : s.z;
    o.w = (sup & 0xFF000000u) ? 0.f : s.w;
    *(float4*)(t0 + (y << 11) + x0) = o;
}
__global__ void k_colmax_upd4(const float* __restrict__ t1,
                              const unsigned char* __restrict__ msup,
                              unsigned char* __restrict__ mask) {
    int t4 = blockIdx.x * 256 + threadIdx.x;
    int y = t4 >> 9, x0 = (t4 & 511) << 2;
    int ya = max(y - 4, 0), yb = min(y + 4, 2047);
    float4 m = make_float4(NEG_INF, NEG_INF, NEG_INF, NEG_INF);
    for (int yy = ya; yy <= yb; yy++) {
        float4 v = *(const float4*)(t1 + (yy << 11) + x0);
        m.x = fmaxf(m.x, v.x); m.y = fmaxf(m.y, v.y);
        m.z = fmaxf(m.z, v.z); m.w = fmaxf(m.w, v.w);
    }
    float4 s = *(const float4*)(g_scores + (y << 11) + x0);
    uchar4 sp = *(const uchar4*)(msup + (y << 11) + x0);
    uchar4 mk = *(uchar4*)(mask + (y << 11) + x0);
    if (!sp.x && s.x == m.x) mk.x = 1;
    if (!sp.y && s.y == m.y) mk.y = 1;
    if (!sp.z && s.z == m.z) mk.z = 1;
    if (!sp.w && s.w == m.w) mk.w = 1;
    *(uchar4*)(mask + (y << 11) + x0) = mk;
}

// ---------------- candidate extraction ----------------
__global__ void k_reset() { g_count = 0; }

__global__ void k_compact(const unsigned char* __restrict__ mask,
                          unsigned long long* __restrict__ keys) {
    int idx = blockIdx.x * 256 + threadIdx.x;
    if (!mask[idx]) return;
    float v = g_scores[idx];
    int y = idx >> 11, x = idx & 2047;
    // reference upper-border check is vacuous (H8*8-4 = 16380 > 2047)
    if (v > THRESH && y >= 4 && x >= 4) {
        int p = atomicAdd(&g_count, 1);
        if (p < CAP)
            keys[p] = ((unsigned long long)__float_as_uint(v) << 32) |
                      (unsigned int)(~(unsigned int)idx);
    }
}

// ---------------- per-chunk bitonic sort (descending) ----------------
__global__ __launch_bounds__(1024) void k_presort(unsigned long long* __restrict__ keys) {
    __shared__ unsigned long long sk[1024];
    const int i = threadIdx.x;
    const int gi = blockIdx.x * 1024 + i;
    int count = min(g_count, CAP);
    sk[i] = (gi < count) ? keys[gi] : 0ULL;
    __syncthreads();
    for (int k = 2; k <= 1024; k <<= 1) {
        for (int j = k >> 1; j > 0; j >>= 1) {
            int ixj = i ^ j;
            if (ixj > i) {
                bool desc = ((i & k) == 0);
                unsigned long long a = sk[i], b = sk[ixj];
                if (desc ? (a < b) : (a > b)) { sk[i] = b; sk[ixj] = a; }
            }
            __syncthreads();
        }
    }
    keys[gi] = sk[i];
}

// ---------------- tournament pair-merge: top-1024 of two sorted 1024 lists -------
__global__ __launch_bounds__(1024) void k_merge_pair(const unsigned long long* __restrict__ src,
                                                     unsigned long long* __restrict__ dst) {
    __shared__ unsigned long long C[1024];
    const int i = threadIdx.x;
    const int b = blockIdx.x;
    unsigned long long a = src[(2*b) * 1024 + i];
    unsigned long long q = src[(2*b + 1) * 1024 + (1023 - i)];
    C[i] = (a > q) ? a : q;        // bitonic; contains top-1024 of the union
    __syncthreads();
    for (int j = 512; j > 0; j >>= 1) {
        int ixj = i ^ j;
        if (ixj > i) {
            unsigned long long u = C[i], v = C[ixj];
            if (u < v) { C[i] = v; C[ixj] = u; }
        }
        __syncthreads();
    }
    dst[b * 1024 + i] = C[i];
}

// ---------------- final output ----------------
__global__ __launch_bounds__(1024) void k_out(const unsigned long long* __restrict__ top,
                                              float* __restrict__ out) {
    const int i = threadIdx.x;
    int count = min(g_count, CAP);
    int nval = min(count, 1024);
    float kx, ky, sc;
    if (i < nval) {
        unsigned long long key = top[i];
        sc = __uint_as_float((unsigned int)(key >> 32));
        unsigned int idx = ~(unsigned int)key;
        kx = (float)(idx & 2047u);
        ky = (float)(idx >> 11);
    } else {
        int j = i - nval;        // top_k padding: -1 score, smallest invalid indices
        sc = -1.0f;
        kx = (float)j;
        ky = 0.0f;
    }
    out[2*i]      = kx;
    out[2*i + 1]  = ky;
    out[2048 + i] = sc;
}

// ---------------- launch ----------------
extern "C" void kernel_launch(void* const* d_in, const int* in_sizes, int n_in,
                              void* d_out, int out_size) {
    const float* enc = (const float*)d_in[0];
    const float* wA  = (const float*)d_in[1];
    const float* bA  = (const float*)d_in[2];
    const float* wB  = (const float*)d_in[3];
    const float* bB  = (const float*)d_in[4];
    float* out = (float*)d_out;

    static unsigned char* P = nullptr;
    static float* scores = nullptr;
    if (P == nullptr) {
        void* pv = nullptr;
        cudaGetSymbolAddress(&pv, g_pool);
        P = (unsigned char*)pv;
        void* sv = nullptr;
        cudaGetSymbolAddress(&sv, g_scores);
        scores = (float*)sv;
        // one-time, uncaptured: allow conv1's 185 KB dynamic smem
        cudaFuncSetAttribute(k_conv1,
                             cudaFuncAttributeMaxDynamicSharedMemorySize,
                             CONV1_DYN_BYTES);
    }
    float* mid = (float*)P;
    float* t0  = (float*)(P + OFF_T0);
    float* t1  = (float*)(P + OFF_T1);
    unsigned char* mask = P + OFF_MASK;
    unsigned char* msup = P + OFF_MSUP;
    unsigned char* mtmp = P + OFF_MTMP;
    unsigned long long* keysA = (unsigned long long*)(P + OFF_KEYSA);
    unsigned long long* keysB = (unsigned long long*)(P + OFF_KEYSB);

    const int V4 = NPIX / 4 / 256;   // 4096 blocks for 4-px/thread kernels
    const int EB = NPIX / 256;       // 16384 blocks per-pixel

    k_reset<<<1, 1>>>();
    k_conv1<<<dim3(8,8,32), dim3(16,16), CONV1_DYN_BYTES>>>(enc, wA, bA, mid);
    k_conv2<<<1024, 256>>>(mid, wB, bB);

    // initial max mask
    k_rowmax4<<<V4, 256>>>(scores, t1);
    k_colmax_eq4<<<V4, 256>>>(t1, mask);

    for (int it = 0; it < 2; it++) {
        k_rowor4<<<V4, 256>>>(mask, mtmp);
        k_color_supp4<<<V4, 256>>>(mtmp, msup, t0);
        k_rowmax4<<<V4, 256>>>(t0, t1);
        k_colmax_upd4<<<V4, 256>>>(t1, msup, mask);
    }

    k_compact<<<EB, 256>>>(mask, keysA);
    k_presort<<<CAP/1024, 1024>>>(keysA);

    // tournament: 128 chunks -> 1 (ping-pong keysA/keysB)
    k_merge_pair<<<64, 1024>>>(keysA, keysB);
    k_merge_pair<<<32, 1024>>>(keysB, keysA);
    k_merge_pair<<<16, 1024>>>(keysA, keysB);
    k_merge_pair<<<8,  1024>>>(keysB, keysA);
    k_merge_pair<<<4,  1024>>>(keysA, keysB);
    k_merge_pair<<<2,  1024>>>(keysB, keysA);
    k_merge_pair<<<1,  1024>>>(keysA, keysB);

    k_out<<<1, 1024>>>(keysB, out);
}